// round 3
// baseline (speedup 1.0000x reference)
#include <cuda_runtime.h>

#define DIM 512
#define NHEAD 16
#define HDIM 32
#define NB 1024
#define NTOK 49
#define MROWS (NB * NTOK)   // 50176
#define QSCALE 0.17677669529663687f  // 32^-0.5

// Scratch (allocation-free rule: __device__ globals)
__device__ float g_Q[(size_t)MROWS * DIM];
__device__ float g_K[(size_t)MROWS * DIM];
__device__ float g_V[(size_t)MROWS * DIM];
__device__ float g_G[(size_t)MROWS * DIM];
__device__ float g_O[(size_t)MROWS * DIM];

// ---------------------------------------------------------------------------
// Tiled SGEMM: C[M,512] = A[M,K] @ B[K, ldb](cols taken at pointer offset) + bias
// BM=BN=128, BK=8, 256 threads, 8x8 microtile in split-64 fragment layout.
// M (=50176) divisible by 128, N (=512) divisible by 128, K (=512) by 8:
// no bounds checks needed.
// ---------------------------------------------------------------------------
__global__ __launch_bounds__(256, 2)
void sgemm128(const float* __restrict__ A, const float* __restrict__ B,
              const float* __restrict__ bias, float* __restrict__ C,
              int K, int ldb) {
    __shared__ float As[8][132];   // transposed A tile, padded (132) for conflict-free stores
    __shared__ float Bs[8][128];

    const int tid = threadIdx.x;
    const int tx = tid & 15;        // 0..15  -> 2 x 4 cols (at tx*4 and 64+tx*4)
    const int ty = tid >> 4;        // 0..15  -> 2 x 4 rows (at ty*4 and 64+ty*4)
    const int m0 = blockIdx.y * 128;
    const int n0 = blockIdx.x * 128;

    const int arow = tid >> 1;          // 0..127
    const int acol = (tid & 1) * 4;     // 0 or 4
    const int brow = tid >> 5;          // 0..7
    const int bcol = (tid & 31) * 4;    // 0..124

    const float* Ap = A + (size_t)(m0 + arow) * K + acol;
    const float* Bp = B + (size_t)brow * ldb + n0 + bcol;

    float acc[8][8];
#pragma unroll
    for (int i = 0; i < 8; i++)
#pragma unroll
        for (int j = 0; j < 8; j++) acc[i][j] = 0.f;

    for (int k0 = 0; k0 < K; k0 += 8) {
        float4 av = *(const float4*)Ap;
        float4 bv = *(const float4*)Bp;
        As[acol + 0][arow] = av.x;
        As[acol + 1][arow] = av.y;
        As[acol + 2][arow] = av.z;
        As[acol + 3][arow] = av.w;
        *(float4*)&Bs[brow][bcol] = bv;
        __syncthreads();

#pragma unroll
        for (int kk = 0; kk < 8; kk++) {
            float ar[8], br[8];
            *(float4*)&ar[0] = *(const float4*)&As[kk][ty * 4];
            *(float4*)&ar[4] = *(const float4*)&As[kk][64 + ty * 4];
            *(float4*)&br[0] = *(const float4*)&Bs[kk][tx * 4];
            *(float4*)&br[4] = *(const float4*)&Bs[kk][64 + tx * 4];
#pragma unroll
            for (int i = 0; i < 8; i++)
#pragma unroll
                for (int j = 0; j < 8; j++)
                    acc[i][j] = fmaf(ar[i], br[j], acc[i][j]);
        }
        __syncthreads();
        Ap += 8;
        Bp += (size_t)8 * ldb;
    }

    // Epilogue: bias + store (C is row-major [M, DIM])
#pragma unroll
    for (int i = 0; i < 8; i++) {
        int r = m0 + ((i < 4) ? (ty * 4 + i) : (64 + ty * 4 + (i - 4)));
#pragma unroll
        for (int jh = 0; jh < 2; jh++) {
            int c = n0 + jh * 64 + tx * 4;
            float4 o;
            o.x = acc[i][jh * 4 + 0] + bias[c + 0];
            o.y = acc[i][jh * 4 + 1] + bias[c + 1];
            o.z = acc[i][jh * 4 + 2] + bias[c + 2];
            o.w = acc[i][jh * 4 + 3] + bias[c + 3];
            *(float4*)&C[(size_t)r * DIM + c] = o;
        }
    }
}

// ---------------------------------------------------------------------------
// Fused attention per (b, h): q = q1*SCALE*g ; S = q@k^T ; P = softmax(S)
// O = P@v + v*a.  All tiles are [49, 32]; scratch is row-major [M, 512] so a
// head slice is 49 rows of 128 contiguous bytes.
// ---------------------------------------------------------------------------
__global__ __launch_bounds__(256)
void attn_kernel(const float* __restrict__ Q1, const float* __restrict__ G,
                 const float* __restrict__ Km, const float* __restrict__ Vm,
                 const float* __restrict__ a_ptr, float* __restrict__ O) {
    __shared__ float qs[NTOK][HDIM + 1];
    __shared__ float ks[NTOK][HDIM + 1];
    __shared__ float vs[NTOK][HDIM + 1];
    __shared__ float S[NTOK][NTOK + 1];

    const int bh = blockIdx.x;
    const int b = bh >> 4;
    const int h = bh & 15;
    const int tid = threadIdx.x;
    const float a = *a_ptr;

    const size_t base = (size_t)b * NTOK * DIM + h * HDIM;

    for (int i = tid; i < NTOK * HDIM; i += 256) {
        int n = i >> 5, d = i & 31;
        size_t idx = base + (size_t)n * DIM + d;
        qs[n][d] = Q1[idx] * QSCALE * G[idx];
        ks[n][d] = Km[idx];
        vs[n][d] = Vm[idx];
    }
    __syncthreads();

    // Scores
    for (int i = tid; i < NTOK * NTOK; i += 256) {
        int n = i / NTOK, m = i - n * NTOK;
        float s = 0.f;
#pragma unroll
        for (int d = 0; d < HDIM; d++) s = fmaf(qs[n][d], ks[m][d], s);
        S[n][m] = s;
    }
    __syncthreads();

    // Softmax: one warp per row, rows strided by 8
    const int warp = tid >> 5, lane = tid & 31;
    for (int n = warp; n < NTOK; n += 8) {
        float v1 = S[n][lane];                                  // lane 0..31 < 49
        float v2 = (lane + 32 < NTOK) ? S[n][lane + 32] : -1e30f;
        float mx = fmaxf(v1, v2);
#pragma unroll
        for (int off = 16; off; off >>= 1)
            mx = fmaxf(mx, __shfl_xor_sync(0xffffffffu, mx, off));
        float e1 = __expf(v1 - mx);
        float e2 = (lane + 32 < NTOK) ? __expf(v2 - mx) : 0.f;
        float sum = e1 + e2;
#pragma unroll
        for (int off = 16; off; off >>= 1)
            sum += __shfl_xor_sync(0xffffffffu, sum, off);
        float inv = 1.f / sum;
        S[n][lane] = e1 * inv;
        if (lane + 32 < NTOK) S[n][lane + 32] = e2 * inv;
    }
    __syncthreads();

    // O = P@v + v*a
    for (int i = tid; i < NTOK * HDIM; i += 256) {
        int n = i >> 5, d = i & 31;
        float o = vs[n][d] * a;
#pragma unroll
        for (int m = 0; m < NTOK; m++) o = fmaf(S[n][m], vs[m][d], o);
        O[base + (size_t)n * DIM + d] = o;
    }
}

// ---------------------------------------------------------------------------
extern "C" void kernel_launch(void* const* d_in, const int* in_sizes, int n_in,
                              void* d_out, int out_size) {
    const float* x     = (const float*)d_in[0];
    const float* x2    = (const float*)d_in[1];
    const float* x3    = (const float*)d_in[2];
    const float* Wqkv  = (const float*)d_in[3];
    const float* bqkv  = (const float*)d_in[4];
    const float* Wqkv2 = (const float*)d_in[5];
    const float* bqkv2 = (const float*)d_in[6];
    const float* Wgw   = (const float*)d_in[7];
    const float* bgw   = (const float*)d_in[8];
    const float* Wproj = (const float*)d_in[9];
    const float* bproj = (const float*)d_in[10];
    const float* a     = (const float*)d_in[11];
    float* out = (float*)d_out;

    float *Q, *K, *V, *G, *O;
    cudaGetSymbolAddress((void**)&Q, g_Q);
    cudaGetSymbolAddress((void**)&K, g_K);
    cudaGetSymbolAddress((void**)&V, g_V);
    cudaGetSymbolAddress((void**)&G, g_G);
    cudaGetSymbolAddress((void**)&O, g_O);

    dim3 gemmGrid(DIM / 128, MROWS / 128);   // (4, 392)

    // K projection: columns [512,1024) of Wqkv (ldb = 1536)
    sgemm128<<<gemmGrid, 256>>>(x,  Wqkv  + DIM,     bqkv  + DIM,     K, DIM, 3 * DIM);
    // Q projection: columns [0,512) of Wqkv2
    sgemm128<<<gemmGrid, 256>>>(x3, Wqkv2,           bqkv2,           Q, DIM, 3 * DIM);
    // V projection: columns [1024,1536) of Wqkv2
    sgemm128<<<gemmGrid, 256>>>(x3, Wqkv2 + 2 * DIM, bqkv2 + 2 * DIM, V, DIM, 3 * DIM);
    // Gate: x2 @ Wgw
    sgemm128<<<gemmGrid, 256>>>(x2, Wgw,             bgw,             G, DIM, DIM);

    // Attention per (b, h)
    attn_kernel<<<NB * NHEAD, 256>>>(Q, G, K, V, a, O);

    // Output projection
    sgemm128<<<gemmGrid, 256>>>(O, Wproj, bproj, out, DIM, DIM);
}

// round 6
// speedup vs baseline: 1.4036x; 1.4036x over previous
#include <cuda_runtime.h>
#include <cuda_bf16.h>

#define DIM 512
#define NHEAD 16
#define HDIM 32
#define NB 1024
#define NTOK 49
#define MROWS (NB * NTOK)   // 50176
#define QSCALE 0.17677669529663687f  // 32^-0.5

// ---------------- scratch (__device__ globals; no allocs allowed) ----------
__device__ float g_Q[(size_t)MROWS * DIM];
__device__ float g_K[(size_t)MROWS * DIM];
__device__ float g_V[(size_t)MROWS * DIM];
__device__ float g_G[(size_t)MROWS * DIM];
__device__ float g_O[(size_t)MROWS * DIM];
__device__ __nv_bfloat16 g_Wh[5][DIM * DIM];
__device__ __nv_bfloat16 g_Wl[5][DIM * DIM];

// ---------------- helpers --------------------------------------------------
__device__ __forceinline__ unsigned smem_u32(const void* p) {
    unsigned a;
    asm("{ .reg .u64 t; cvta.to.shared.u64 t, %1; cvt.u32.u64 %0, t; }" : "=r"(a) : "l"(p));
    return a;
}
__device__ __forceinline__ void sts64(unsigned a, unsigned x, unsigned y) {
    asm volatile("st.shared.v2.b32 [%0], {%1,%2};" :: "r"(a), "r"(x), "r"(y) : "memory");
}
__device__ __forceinline__ void sts128(unsigned a, uint4 v) {
    asm volatile("st.shared.v4.b32 [%0], {%1,%2,%3,%4};" :: "r"(a), "r"(v.x), "r"(v.y), "r"(v.z), "r"(v.w) : "memory");
}
__device__ __forceinline__ unsigned pack_bf16(__nv_bfloat16 a, __nv_bfloat16 b) {
    return (unsigned)__bfloat16_as_ushort(a) | ((unsigned)__bfloat16_as_ushort(b) << 16);
}
__device__ __forceinline__ void ldsm4(unsigned* r, unsigned addr) {
    asm volatile("ldmatrix.sync.aligned.m8n8.x4.shared.b16 {%0,%1,%2,%3}, [%4];"
        : "=r"(r[0]), "=r"(r[1]), "=r"(r[2]), "=r"(r[3]) : "r"(addr));
}
__device__ __forceinline__ void mma16816(float* d, const unsigned* a, unsigned b0, unsigned b1) {
    asm volatile("mma.sync.aligned.m16n8k16.row.col.f32.bf16.bf16.f32 "
        "{%0,%1,%2,%3}, {%4,%5,%6,%7}, {%8,%9}, {%0,%1,%2,%3};"
        : "+f"(d[0]), "+f"(d[1]), "+f"(d[2]), "+f"(d[3])
        : "r"(a[0]), "r"(a[1]), "r"(a[2]), "r"(a[3]), "r"(b0), "r"(b1));
}

// ---------------------------------------------------------------------------
// Weight transpose + hi/lo split: T[n*512+k] = split(W[k*ldb + n])
// ---------------------------------------------------------------------------
__global__ void tsplit(const float* __restrict__ W, int ldb,
                       __nv_bfloat16* __restrict__ Th, __nv_bfloat16* __restrict__ Tl) {
    __shared__ float t[32][33];
    int k0 = blockIdx.x * 32, n0 = blockIdx.y * 32;
    int tx = threadIdx.x, ty = threadIdx.y;
#pragma unroll
    for (int j = 0; j < 32; j += 8)
        t[ty + j][tx] = W[(size_t)(k0 + ty + j) * ldb + n0 + tx];
    __syncthreads();
#pragma unroll
    for (int j = 0; j < 32; j += 8) {
        float v = t[tx][ty + j];
        __nv_bfloat16 h = __float2bfloat16(v);
        __nv_bfloat16 l = __float2bfloat16(v - __bfloat162float(h));
        size_t o = (size_t)(n0 + ty + j) * DIM + k0 + tx;
        Th[o] = h; Tl[o] = l;
    }
}

// ---------------------------------------------------------------------------
// Warp-MMA bf16 GEMM (3-pass split => fp32-grade accuracy):
//   C[M,512] = A[M,512](fp32, split on the fly) @ W + bias
//   Weights pre-split & transposed: Bh/Bl are [512 N-rows][512 K] bf16.
//   CTA tile 128x128, K-chunk 64. 8 warps, warp tile 64x32 (m16n8k16).
//   smem rows are 128B (64 bf16); swizzle: 16B-chunk ^= (row & 7).
// ---------------------------------------------------------------------------
#define OFF_AH 0
#define OFF_AL 16384
#define OFF_BH 32768
#define OFF_BL 49152
#define GEMM_SMEM 65536

__global__ void __launch_bounds__(256, 2)
gemm_tc(const float* __restrict__ A,
        const __nv_bfloat16* __restrict__ Bh, const __nv_bfloat16* __restrict__ Bl,
        const float* __restrict__ bias, float* __restrict__ C) {
    extern __shared__ char smem[];
    const unsigned sb = smem_u32(smem);
    const int tid = threadIdx.x, wid = tid >> 5, lane = tid & 31;
    const int n0 = blockIdx.x * 128, m0 = blockIdx.y * 128;

    const int wm = (wid >> 2) * 64;     // warp M offset (0 or 64)
    const int wn = (wid & 3) * 32;      // warp N offset (0,32,64,96)

    // ldmatrix per-lane geometry (x4: lane groups of 8 give the 4 matrices)
    const int grp = lane >> 3, lr = lane & 7;
    const int rA = wm + lr + ((grp & 1) << 3);        // A row for this lane (+t*16)
    const int rB = wn + lr + ((grp & 1) << 3);        // B row (+0 / +16)
    const int cadd = (grp >> 1) & 1;                  // +1 chunk for k+8 matrices
    const int amod = rA & 7;                          // row&7 (invariant under +16)
    const int bmod = rB & 7;

    float acc[4][4][4];
#pragma unroll
    for (int t = 0; t < 4; t++)
#pragma unroll
        for (int u = 0; u < 4; u++)
#pragma unroll
            for (int i = 0; i < 4; i++) acc[t][u][i] = 0.f;

    for (int c = 0; c < 8; ++c) {
        const int k0 = c * 64;
        // ---- fill: A fp32 -> hi/lo bf16 (swizzled), B pre-split bf16 ----
#pragma unroll
        for (int g = tid; g < 2048; g += 256) {
            int row = g >> 4, seg = g & 15;
            float4 v = *(const float4*)(A + (size_t)(m0 + row) * DIM + k0 + seg * 4);
            __nv_bfloat16 h0 = __float2bfloat16(v.x), h1 = __float2bfloat16(v.y);
            __nv_bfloat16 h2 = __float2bfloat16(v.z), h3 = __float2bfloat16(v.w);
            __nv_bfloat16 l0 = __float2bfloat16(v.x - __bfloat162float(h0));
            __nv_bfloat16 l1 = __float2bfloat16(v.y - __bfloat162float(h1));
            __nv_bfloat16 l2 = __float2bfloat16(v.z - __bfloat162float(h2));
            __nv_bfloat16 l3 = __float2bfloat16(v.w - __bfloat162float(h3));
            unsigned off = row * 128 + seg * 8;
            unsigned sw = off ^ ((off >> 3) & 0x70);
            sts64(sb + OFF_AH + sw, pack_bf16(h0, h1), pack_bf16(h2, h3));
            sts64(sb + OFF_AL + sw, pack_bf16(l0, l1), pack_bf16(l2, l3));
        }
#pragma unroll
        for (int g = tid; g < 1024; g += 256) {
            int row = g >> 3, seg = g & 7;
            size_t src = (size_t)(n0 + row) * DIM + k0 + seg * 8;
            uint4 vh = *(const uint4*)(Bh + src);
            uint4 vl = *(const uint4*)(Bl + src);
            unsigned off = row * 128 + seg * 16;
            unsigned sw = off ^ ((off >> 3) & 0x70);
            sts128(sb + OFF_BH + sw, vh);
            sts128(sb + OFF_BL + sw, vl);
        }
        __syncthreads();

        // ---- 3 passes: (Ah,Bh), (Ah,Bl), (Al,Bh) ----
#pragma unroll
        for (int p = 0; p < 3; ++p) {
            const unsigned abase = sb + (p == 2 ? OFF_AL : OFF_AH);
            const unsigned bbase = sb + (p == 1 ? OFF_BL : OFF_BH);
#pragma unroll
            for (int ks = 0; ks < 4; ++ks) {
                const int chk = ks * 2 + cadd;
                unsigned bf0[4], bf1[4];
                ldsm4(bf0, bbase + rB * 128 + (((chk) ^ bmod) << 4));
                ldsm4(bf1, bbase + (rB + 16) * 128 + (((chk) ^ bmod) << 4));
                unsigned af[4][4];
#pragma unroll
                for (int t = 0; t < 4; ++t)
                    ldsm4(af[t], abase + (rA + t * 16) * 128 + (((chk) ^ amod) << 4));
#pragma unroll
                for (int t = 0; t < 4; ++t) {
                    mma16816(acc[t][0], af[t], bf0[0], bf0[2]);
                    mma16816(acc[t][1], af[t], bf0[1], bf0[3]);
                    mma16816(acc[t][2], af[t], bf1[0], bf1[2]);
                    mma16816(acc[t][3], af[t], bf1[1], bf1[3]);
                }
            }
        }
        __syncthreads();
    }

    // ---- epilogue: direct stores with bias (C layout of m16n8) ----
#pragma unroll
    for (int u = 0; u < 4; ++u) {
        const int col = n0 + wn + u * 8 + (lane & 3) * 2;
        const float bx = bias[col], by = bias[col + 1];
#pragma unroll
        for (int t = 0; t < 4; ++t) {
            const int row = m0 + wm + t * 16 + (lane >> 2);
            float2 o0 = { acc[t][u][0] + bx, acc[t][u][1] + by };
            float2 o1 = { acc[t][u][2] + bx, acc[t][u][3] + by };
            *(float2*)(C + (size_t)row * DIM + col) = o0;
            *(float2*)(C + (size_t)(row + 8) * DIM + col) = o1;
        }
    }
}

// ---------------------------------------------------------------------------
// Fused attention per (b, h) — unchanged from passing baseline.
// ---------------------------------------------------------------------------
__global__ __launch_bounds__(256)
void attn_kernel(const float* __restrict__ Q1, const float* __restrict__ G,
                 const float* __restrict__ Km, const float* __restrict__ Vm,
                 const float* __restrict__ a_ptr, float* __restrict__ O) {
    __shared__ float qs[NTOK][HDIM + 1];
    __shared__ float ks[NTOK][HDIM + 1];
    __shared__ float vs[NTOK][HDIM + 1];
    __shared__ float S[NTOK][NTOK + 1];

    const int bh = blockIdx.x;
    const int b = bh >> 4;
    const int h = bh & 15;
    const int tid = threadIdx.x;
    const float a = *a_ptr;

    const size_t base = (size_t)b * NTOK * DIM + h * HDIM;

    for (int i = tid; i < NTOK * HDIM; i += 256) {
        int n = i >> 5, d = i & 31;
        size_t idx = base + (size_t)n * DIM + d;
        qs[n][d] = Q1[idx] * QSCALE * G[idx];
        ks[n][d] = Km[idx];
        vs[n][d] = Vm[idx];
    }
    __syncthreads();

    for (int i = tid; i < NTOK * NTOK; i += 256) {
        int n = i / NTOK, m = i - n * NTOK;
        float s = 0.f;
#pragma unroll
        for (int d = 0; d < HDIM; d++) s = fmaf(qs[n][d], ks[m][d], s);
        S[n][m] = s;
    }
    __syncthreads();

    const int warp = tid >> 5, lane = tid & 31;
    for (int n = warp; n < NTOK; n += 8) {
        float v1 = S[n][lane];
        float v2 = (lane + 32 < NTOK) ? S[n][lane + 32] : -1e30f;
        float mx = fmaxf(v1, v2);
#pragma unroll
        for (int off = 16; off; off >>= 1)
            mx = fmaxf(mx, __shfl_xor_sync(0xffffffffu, mx, off));
        float e1 = __expf(v1 - mx);
        float e2 = (lane + 32 < NTOK) ? __expf(v2 - mx) : 0.f;
        float sum = e1 + e2;
#pragma unroll
        for (int off = 16; off; off >>= 1)
            sum += __shfl_xor_sync(0xffffffffu, sum, off);
        float inv = 1.f / sum;
        S[n][lane] = e1 * inv;
        if (lane + 32 < NTOK) S[n][lane + 32] = e2 * inv;
    }
    __syncthreads();

    for (int i = tid; i < NTOK * HDIM; i += 256) {
        int n = i >> 5, d = i & 31;
        float o = vs[n][d] * a;
#pragma unroll
        for (int m = 0; m < NTOK; m++) o = fmaf(S[n][m], vs[m][d], o);
        O[base + (size_t)n * DIM + d] = o;
    }
}

// ---------------------------------------------------------------------------
extern "C" void kernel_launch(void* const* d_in, const int* in_sizes, int n_in,
                              void* d_out, int out_size) {
    const float* x     = (const float*)d_in[0];
    const float* x2    = (const float*)d_in[1];
    const float* x3    = (const float*)d_in[2];
    const float* Wqkv  = (const float*)d_in[3];
    const float* bqkv  = (const float*)d_in[4];
    const float* Wqkv2 = (const float*)d_in[5];
    const float* bqkv2 = (const float*)d_in[6];
    const float* Wgw   = (const float*)d_in[7];
    const float* bgw   = (const float*)d_in[8];
    const float* Wproj = (const float*)d_in[9];
    const float* bproj = (const float*)d_in[10];
    const float* a     = (const float*)d_in[11];
    float* out = (float*)d_out;

    float *Q, *K, *V, *G, *O;
    cudaGetSymbolAddress((void**)&Q, g_Q);
    cudaGetSymbolAddress((void**)&K, g_K);
    cudaGetSymbolAddress((void**)&V, g_V);
    cudaGetSymbolAddress((void**)&G, g_G);
    cudaGetSymbolAddress((void**)&O, g_O);
    __nv_bfloat16 *Wh, *Wl;
    cudaGetSymbolAddress((void**)&Wh, g_Wh);
    cudaGetSymbolAddress((void**)&Wl, g_Wl);

    cudaFuncSetAttribute(gemm_tc, cudaFuncAttributeMaxDynamicSharedMemorySize, GEMM_SMEM);

    dim3 tsG(16, 16), tsB(32, 8);
    // 0:K (Wqkv cols [512,1024)), 1:Q (Wqkv2 [0,512)), 2:V (Wqkv2 [1024,1536)),
    // 3:gate (Wgw), 4:proj (Wproj)
    tsplit<<<tsG, tsB>>>(Wqkv  + DIM,     3 * DIM, Wh + 0 * DIM * DIM, Wl + 0 * DIM * DIM);
    tsplit<<<tsG, tsB>>>(Wqkv2,           3 * DIM, Wh + 1 * DIM * DIM, Wl + 1 * DIM * DIM);
    tsplit<<<tsG, tsB>>>(Wqkv2 + 2 * DIM, 3 * DIM, Wh + 2 * DIM * DIM, Wl + 2 * DIM * DIM);
    tsplit<<<tsG, tsB>>>(Wgw,             DIM,     Wh + 3 * DIM * DIM, Wl + 3 * DIM * DIM);
    tsplit<<<tsG, tsB>>>(Wproj,           DIM,     Wh + 4 * DIM * DIM, Wl + 4 * DIM * DIM);

    dim3 gg(DIM / 128, MROWS / 128);   // (4, 392)
    gemm_tc<<<gg, 256, GEMM_SMEM>>>(x,  Wh + 0 * DIM * DIM, Wl + 0 * DIM * DIM, bqkv + DIM,      K);
    gemm_tc<<<gg, 256, GEMM_SMEM>>>(x3, Wh + 1 * DIM * DIM, Wl + 1 * DIM * DIM, bqkv2,           Q);
    gemm_tc<<<gg, 256, GEMM_SMEM>>>(x3, Wh + 2 * DIM * DIM, Wl + 2 * DIM * DIM, bqkv2 + 2 * DIM, V);
    gemm_tc<<<gg, 256, GEMM_SMEM>>>(x2, Wh + 3 * DIM * DIM, Wl + 3 * DIM * DIM, bgw,             G);

    attn_kernel<<<NB * NHEAD, 256>>>(Q, G, K, V, a, O);

    gemm_tc<<<gg, 256, GEMM_SMEM>>>(O,  Wh + 4 * DIM * DIM, Wl + 4 * DIM * DIM, bproj,           out);
}

// round 7
// speedup vs baseline: 1.9314x; 1.3760x over previous
#include <cuda_runtime.h>
#include <cuda_bf16.h>

#define DIM 512
#define NHEAD 16
#define HDIM 32
#define NB 1024
#define NTOK 49
#define MROWS (NB * NTOK)   // 50176
#define QSCALE 0.17677669529663687f  // 32^-0.5

// ---------------- scratch (__device__ globals; no allocs allowed) ----------
__device__ float g_Q[(size_t)MROWS * DIM];
__device__ float g_K[(size_t)MROWS * DIM];
__device__ float g_V[(size_t)MROWS * DIM];
__device__ float g_G[(size_t)MROWS * DIM];
__device__ float g_O[(size_t)MROWS * DIM];
__device__ __nv_bfloat16 g_Wh[5][DIM * DIM];
__device__ __nv_bfloat16 g_Wl[5][DIM * DIM];

// ---------------- helpers --------------------------------------------------
__device__ __forceinline__ unsigned smem_u32(const void* p) {
    unsigned a;
    asm("{ .reg .u64 t; cvta.to.shared.u64 t, %1; cvt.u32.u64 %0, t; }" : "=r"(a) : "l"(p));
    return a;
}
__device__ __forceinline__ void sts64(unsigned a, unsigned x, unsigned y) {
    asm volatile("st.shared.v2.b32 [%0], {%1,%2};" :: "r"(a), "r"(x), "r"(y) : "memory");
}
__device__ __forceinline__ unsigned pack_bf16(__nv_bfloat16 a, __nv_bfloat16 b) {
    return (unsigned)__bfloat16_as_ushort(a) | ((unsigned)__bfloat16_as_ushort(b) << 16);
}
__device__ __forceinline__ void ldsm4(unsigned* r, unsigned addr) {
    asm volatile("ldmatrix.sync.aligned.m8n8.x4.shared.b16 {%0,%1,%2,%3}, [%4];"
        : "=r"(r[0]), "=r"(r[1]), "=r"(r[2]), "=r"(r[3]) : "r"(addr));
}
__device__ __forceinline__ void mma16816(float* d, const unsigned* a, unsigned b0, unsigned b1) {
    asm volatile("mma.sync.aligned.m16n8k16.row.col.f32.bf16.bf16.f32 "
        "{%0,%1,%2,%3}, {%4,%5,%6,%7}, {%8,%9}, {%0,%1,%2,%3};"
        : "+f"(d[0]), "+f"(d[1]), "+f"(d[2]), "+f"(d[3])
        : "r"(a[0]), "r"(a[1]), "r"(a[2]), "r"(a[3]), "r"(b0), "r"(b1));
}
__device__ __forceinline__ void cpa16(unsigned saddr, const void* g) {
    asm volatile("cp.async.cg.shared.global [%0], [%1], 16;" :: "r"(saddr), "l"(g));
}
#define CP_COMMIT() asm volatile("cp.async.commit_group;" ::: "memory")
#define CP_WAIT0()  asm volatile("cp.async.wait_group 0;" ::: "memory")

// ---------------------------------------------------------------------------
// Weight transpose + hi/lo split: T[n*512+k] = split(W[k*ldb + n])
// ---------------------------------------------------------------------------
__global__ void tsplit(const float* __restrict__ W, int ldb,
                       __nv_bfloat16* __restrict__ Th, __nv_bfloat16* __restrict__ Tl) {
    __shared__ float t[32][33];
    int k0 = blockIdx.x * 32, n0 = blockIdx.y * 32;
    int tx = threadIdx.x, ty = threadIdx.y;
#pragma unroll
    for (int j = 0; j < 32; j += 8)
        t[ty + j][tx] = W[(size_t)(k0 + ty + j) * ldb + n0 + tx];
    __syncthreads();
#pragma unroll
    for (int j = 0; j < 32; j += 8) {
        float v = t[tx][ty + j];
        __nv_bfloat16 h = __float2bfloat16(v);
        __nv_bfloat16 l = __float2bfloat16(v - __bfloat162float(h));
        size_t o = (size_t)(n0 + ty + j) * DIM + k0 + tx;
        Th[o] = h; Tl[o] = l;
    }
}

// ---------------------------------------------------------------------------
// Warp-MMA bf16 GEMM (3-pass hi/lo split -> fp32-grade accuracy).
//   C[M, 512] = A[M, 512](fp32, split on the fly) @ W + bias
//   Bh/Bl: K-major [Ntot rows][512 K] bf16 (pre-split, pre-transposed).
//   CTA tile 128x128, K-chunk 64, 8 warps (warp tile 64x32).
//   nsplit: output column splitting for fused launches (n0 >= nsplit -> C1).
// ---------------------------------------------------------------------------
#define OFF_AH 0
#define OFF_AL 16384
#define OFF_BH 32768
#define OFF_BL 49152
#define GEMM_SMEM 65536

__global__ void __launch_bounds__(256, 2)
gemm_tc(const float* __restrict__ A,
        const __nv_bfloat16* __restrict__ Bh, const __nv_bfloat16* __restrict__ Bl,
        const float* __restrict__ bias0, const float* __restrict__ bias1,
        float* __restrict__ C0, float* __restrict__ C1, int nsplit) {
    extern __shared__ char smem[];
    const unsigned sb = smem_u32(smem);
    const int tid = threadIdx.x, wid = tid >> 5, lane = tid & 31;
    const int n0 = blockIdx.x * 128, m0 = blockIdx.y * 128;

    const float* bias = (n0 < nsplit) ? bias0 : bias1;
    float* C = (n0 < nsplit) ? C0 : C1;
    const int nc0 = (n0 < nsplit) ? n0 : n0 - nsplit;

    const int wm = (wid >> 2) * 64;     // warp M offset (0 or 64)
    const int wn = (wid & 3) * 32;      // warp N offset (0,32,64,96)

    // ldmatrix per-lane geometry
    const int grp = lane >> 3, lr = lane & 7;
    const int rA = wm + lr + ((grp & 1) << 3);
    const int rB = wn + lr + ((grp & 1) << 3);
    const int cadd = (grp >> 1) & 1;
    const int amod = rA & 7;
    const int bmod = rB & 7;

    float acc[4][4][4];
#pragma unroll
    for (int t = 0; t < 4; t++)
#pragma unroll
        for (int u = 0; u < 4; u++)
#pragma unroll
            for (int i = 0; i < 4; i++) acc[t][u][i] = 0.f;

    for (int c = 0; c < 8; ++c) {
        const int k0 = c * 64;
        // ---- B fill: straight cp.async GMEM -> smem (no reg round trip) ----
#pragma unroll
        for (int g = tid; g < 1024; g += 256) {
            int row = g >> 3, seg = g & 7;
            size_t src = (size_t)(n0 + row) * DIM + k0 + seg * 8;
            unsigned off = row * 128 + seg * 16;
            unsigned sw = off ^ ((off >> 3) & 0x70);
            cpa16(sb + OFF_BH + sw, Bh + src);
            cpa16(sb + OFF_BL + sw, Bl + src);
        }
        CP_COMMIT();
        // ---- A fill: fp32 -> hi/lo bf16 (swizzled) ----
#pragma unroll
        for (int g = tid; g < 2048; g += 256) {
            int row = g >> 4, seg = g & 15;
            float4 v = *(const float4*)(A + (size_t)(m0 + row) * DIM + k0 + seg * 4);
            __nv_bfloat16 h0 = __float2bfloat16(v.x), h1 = __float2bfloat16(v.y);
            __nv_bfloat16 h2 = __float2bfloat16(v.z), h3 = __float2bfloat16(v.w);
            __nv_bfloat16 l0 = __float2bfloat16(v.x - __bfloat162float(h0));
            __nv_bfloat16 l1 = __float2bfloat16(v.y - __bfloat162float(h1));
            __nv_bfloat16 l2 = __float2bfloat16(v.z - __bfloat162float(h2));
            __nv_bfloat16 l3 = __float2bfloat16(v.w - __bfloat162float(h3));
            unsigned off = row * 128 + seg * 8;
            unsigned sw = off ^ ((off >> 3) & 0x70);
            sts64(sb + OFF_AH + sw, pack_bf16(h0, h1), pack_bf16(h2, h3));
            sts64(sb + OFF_AL + sw, pack_bf16(l0, l1), pack_bf16(l2, l3));
        }
        CP_WAIT0();
        __syncthreads();

        // ---- MMA: per kstep load Ah,Bh,Bl; run hi*hi, hi*lo; reload Al; lo*hi
#pragma unroll
        for (int ks = 0; ks < 4; ++ks) {
            const int chk = ks * 2 + cadd;
            const unsigned aoff = (unsigned)(rA * 128) + (((chk) ^ amod) << 4);
            const unsigned boff = (unsigned)(rB * 128) + (((chk) ^ bmod) << 4);
            unsigned af[4][4], bh0[4], bh1[4], bl0[4], bl1[4];
            ldsm4(bh0, sb + OFF_BH + boff);
            ldsm4(bh1, sb + OFF_BH + boff + 16 * 128);
            ldsm4(bl0, sb + OFF_BL + boff);
            ldsm4(bl1, sb + OFF_BL + boff + 16 * 128);
#pragma unroll
            for (int t = 0; t < 4; ++t)
                ldsm4(af[t], sb + OFF_AH + aoff + t * 16 * 128);
#pragma unroll
            for (int t = 0; t < 4; ++t) {
                mma16816(acc[t][0], af[t], bh0[0], bh0[2]);
                mma16816(acc[t][1], af[t], bh0[1], bh0[3]);
                mma16816(acc[t][2], af[t], bh1[0], bh1[2]);
                mma16816(acc[t][3], af[t], bh1[1], bh1[3]);
            }
#pragma unroll
            for (int t = 0; t < 4; ++t) {
                mma16816(acc[t][0], af[t], bl0[0], bl0[2]);
                mma16816(acc[t][1], af[t], bl0[1], bl0[3]);
                mma16816(acc[t][2], af[t], bl1[0], bl1[2]);
                mma16816(acc[t][3], af[t], bl1[1], bl1[3]);
            }
#pragma unroll
            for (int t = 0; t < 4; ++t)
                ldsm4(af[t], sb + OFF_AL + aoff + t * 16 * 128);
#pragma unroll
            for (int t = 0; t < 4; ++t) {
                mma16816(acc[t][0], af[t], bh0[0], bh0[2]);
                mma16816(acc[t][1], af[t], bh0[1], bh0[3]);
                mma16816(acc[t][2], af[t], bh1[0], bh1[2]);
                mma16816(acc[t][3], af[t], bh1[1], bh1[3]);
            }
        }
        __syncthreads();
    }

    // ---- epilogue: direct stores with bias ----
#pragma unroll
    for (int u = 0; u < 4; ++u) {
        const int col = nc0 + wn + u * 8 + (lane & 3) * 2;
        const float bx = bias[col], by = bias[col + 1];
#pragma unroll
        for (int t = 0; t < 4; ++t) {
            const int row = m0 + wm + t * 16 + (lane >> 2);
            float2 o0 = { acc[t][u][0] + bx, acc[t][u][1] + by };
            float2 o1 = { acc[t][u][2] + bx, acc[t][u][3] + by };
            *(float2*)(C + (size_t)row * DIM + col) = o0;
            *(float2*)(C + (size_t)(row + 8) * DIM + col) = o1;
        }
    }
}

// ---------------------------------------------------------------------------
// Fused attention per (b, h) — unchanged.
// ---------------------------------------------------------------------------
__global__ __launch_bounds__(256)
void attn_kernel(const float* __restrict__ Q1, const float* __restrict__ G,
                 const float* __restrict__ Km, const float* __restrict__ Vm,
                 const float* __restrict__ a_ptr, float* __restrict__ O) {
    __shared__ float qs[NTOK][HDIM + 1];
    __shared__ float ks[NTOK][HDIM + 1];
    __shared__ float vs[NTOK][HDIM + 1];
    __shared__ float S[NTOK][NTOK + 1];

    const int bh = blockIdx.x;
    const int b = bh >> 4;
    const int h = bh & 15;
    const int tid = threadIdx.x;
    const float a = *a_ptr;

    const size_t base = (size_t)b * NTOK * DIM + h * HDIM;

    for (int i = tid; i < NTOK * HDIM; i += 256) {
        int n = i >> 5, d = i & 31;
        size_t idx = base + (size_t)n * DIM + d;
        qs[n][d] = Q1[idx] * QSCALE * G[idx];
        ks[n][d] = Km[idx];
        vs[n][d] = Vm[idx];
    }
    __syncthreads();

    for (int i = tid; i < NTOK * NTOK; i += 256) {
        int n = i / NTOK, m = i - n * NTOK;
        float s = 0.f;
#pragma unroll
        for (int d = 0; d < HDIM; d++) s = fmaf(qs[n][d], ks[m][d], s);
        S[n][m] = s;
    }
    __syncthreads();

    const int warp = tid >> 5, lane = tid & 31;
    for (int n = warp; n < NTOK; n += 8) {
        float v1 = S[n][lane];
        float v2 = (lane + 32 < NTOK) ? S[n][lane + 32] : -1e30f;
        float mx = fmaxf(v1, v2);
#pragma unroll
        for (int off = 16; off; off >>= 1)
            mx = fmaxf(mx, __shfl_xor_sync(0xffffffffu, mx, off));
        float e1 = __expf(v1 - mx);
        float e2 = (lane + 32 < NTOK) ? __expf(v2 - mx) : 0.f;
        float sum = e1 + e2;
#pragma unroll
        for (int off = 16; off; off >>= 1)
            sum += __shfl_xor_sync(0xffffffffu, sum, off);
        float inv = 1.f / sum;
        S[n][lane] = e1 * inv;
        if (lane + 32 < NTOK) S[n][lane + 32] = e2 * inv;
    }
    __syncthreads();

    for (int i = tid; i < NTOK * HDIM; i += 256) {
        int n = i >> 5, d = i & 31;
        float o = vs[n][d] * a;
#pragma unroll
        for (int m = 0; m < NTOK; m++) o = fmaf(S[n][m], vs[m][d], o);
        O[base + (size_t)n * DIM + d] = o;
    }
}

// ---------------------------------------------------------------------------
extern "C" void kernel_launch(void* const* d_in, const int* in_sizes, int n_in,
                              void* d_out, int out_size) {
    const float* x     = (const float*)d_in[0];
    const float* x2    = (const float*)d_in[1];
    const float* x3    = (const float*)d_in[2];
    const float* Wqkv  = (const float*)d_in[3];
    const float* bqkv  = (const float*)d_in[4];
    const float* Wqkv2 = (const float*)d_in[5];
    const float* bqkv2 = (const float*)d_in[6];
    const float* Wgw   = (const float*)d_in[7];
    const float* bgw   = (const float*)d_in[8];
    const float* Wproj = (const float*)d_in[9];
    const float* bproj = (const float*)d_in[10];
    const float* a     = (const float*)d_in[11];
    float* out = (float*)d_out;

    float *Q, *K, *V, *G, *O;
    cudaGetSymbolAddress((void**)&Q, g_Q);
    cudaGetSymbolAddress((void**)&K, g_K);
    cudaGetSymbolAddress((void**)&V, g_V);
    cudaGetSymbolAddress((void**)&G, g_G);
    cudaGetSymbolAddress((void**)&O, g_O);
    __nv_bfloat16 *Wh, *Wl;
    cudaGetSymbolAddress((void**)&Wh, g_Wh);
    cudaGetSymbolAddress((void**)&Wl, g_Wl);

    cudaFuncSetAttribute(gemm_tc, cudaFuncAttributeMaxDynamicSharedMemorySize, GEMM_SMEM);

    dim3 tsG(16, 16), tsB(32, 8);
    // 0:K (Wqkv cols [512,1024)); 1:Q (Wqkv2 [0,512)); 2:V (Wqkv2 [1024,1536))
    //   -> slots 1,2 are contiguous = stacked [1024,512] for the fused QV GEMM
    // 3:gate (Wgw); 4:proj (Wproj)
    tsplit<<<tsG, tsB>>>(Wqkv  + DIM,     3 * DIM, Wh + 0 * DIM * DIM, Wl + 0 * DIM * DIM);
    tsplit<<<tsG, tsB>>>(Wqkv2,           3 * DIM, Wh + 1 * DIM * DIM, Wl + 1 * DIM * DIM);
    tsplit<<<tsG, tsB>>>(Wqkv2 + 2 * DIM, 3 * DIM, Wh + 2 * DIM * DIM, Wl + 2 * DIM * DIM);
    tsplit<<<tsG, tsB>>>(Wgw,             DIM,     Wh + 3 * DIM * DIM, Wl + 3 * DIM * DIM);
    tsplit<<<tsG, tsB>>>(Wproj,           DIM,     Wh + 4 * DIM * DIM, Wl + 4 * DIM * DIM);

    const int BIG = 1 << 30;
    dim3 gg(DIM / 128, MROWS / 128);    // (4, 392)
    dim3 gqv(2 * DIM / 128, MROWS / 128);  // (8, 392) fused Q|V

    // K projection
    gemm_tc<<<gg,  256, GEMM_SMEM>>>(x,  Wh + 0 * DIM * DIM, Wl + 0 * DIM * DIM,
                                     bqkv + DIM, nullptr, K, nullptr, BIG);
    // Q and V projections fused (stacked weights, split outputs)
    gemm_tc<<<gqv, 256, GEMM_SMEM>>>(x3, Wh + 1 * DIM * DIM, Wl + 1 * DIM * DIM,
                                     bqkv2, bqkv2 + 2 * DIM, Q, V, DIM);
    // Gate
    gemm_tc<<<gg,  256, GEMM_SMEM>>>(x2, Wh + 3 * DIM * DIM, Wl + 3 * DIM * DIM,
                                     bgw, nullptr, G, nullptr, BIG);

    attn_kernel<<<NB * NHEAD, 256>>>(Q, G, K, V, a, O);

    // Output projection
    gemm_tc<<<gg,  256, GEMM_SMEM>>>(O,  Wh + 4 * DIM * DIM, Wl + 4 * DIM * DIM,
                                     bproj, nullptr, out, nullptr, BIG);
}